// round 3
// baseline (speedup 1.0000x reference)
#include <cuda_runtime.h>
#include <math.h>

#define B_SZ   2
#define S_LEN  2048
#define E_DIM  1024
#define H_NUM  16
#define D_HEAD 64
#define QKV_DIM 3072   // 3 * E_DIM

// Scratch (allocation-free rule: device globals)
__device__ float g_qkv[B_SZ * S_LEN * QKV_DIM];   // [B,S,3E]
__device__ float g_attn[B_SZ * S_LEN * E_DIM];    // [B,S,E]

// ---------------------------------------------------------------------------
// helpers
// ---------------------------------------------------------------------------
__device__ __forceinline__ unsigned f2tf(float f) {
    unsigned u;
    asm("cvt.rna.tf32.f32 %0, %1;" : "=r"(u) : "f"(f));
    return u;
}

// D += A(16x8 tf32 row) * B(8x8 tf32 col), fp32 accumulate, in-place
__device__ __forceinline__ void mma8(float* d, const unsigned* a, const unsigned* b) {
    asm volatile(
        "mma.sync.aligned.m16n8k8.row.col.f32.tf32.tf32.f32 "
        "{%0,%1,%2,%3},{%4,%5,%6,%7},{%8,%9},{%0,%1,%2,%3};"
        : "+f"(d[0]), "+f"(d[1]), "+f"(d[2]), "+f"(d[3])
        : "r"(a[0]), "r"(a[1]), "r"(a[2]), "r"(a[3]), "r"(b[0]), "r"(b[1]));
}

// ---------------------------------------------------------------------------
// Tensor-core GEMM: C[M,N] = A[M,K] @ W[N,K]^T + bias[N]
// 128x128x16 tiles, 8 warps, warp tile 64x32, frag-major smem, double buffer.
// Frag-major layouts (stage = 2048 words each):
//   A frag (ks 0..1, mt16 0..7):  word ((ks*8+mt)*32 + lane)*4 + reg  (LDS.128)
//   B frag (ks 0..1, nt8 0..15):  word ((ks*16+nt)*32 + lane)*2 + reg (LDS.64)
// ---------------------------------------------------------------------------
__global__ __launch_bounds__(256, 2)
void gemm_tc(const float* __restrict__ A, const float* __restrict__ W,
             const float* __restrict__ bias, float* __restrict__ C,
             int M, int N, int K)
{
    __shared__ unsigned As[2][2048];
    __shared__ unsigned Bs[2][2048];

    const int tid  = threadIdx.x;
    const int lane = tid & 31;
    const int w    = tid >> 5;
    const int wr   = w >> 2;     // 0..1
    const int wc   = w & 3;      // 0..3
    const int g    = lane >> 2;
    const int qp   = lane & 3;
    const int m0   = blockIdx.y * 128;
    const int n0   = blockIdx.x * 128;

    // gmem mapping: row r = tid>>1 (0..127), two float4 at k = c0, c0+4
    const int r  = tid >> 1;
    const int c0 = (tid & 1) * 8;
    const float* Arow = A + (size_t)(m0 + r) * K;
    const float* Wrow = W + (size_t)(n0 + r) * K;

    // store-side constants
    const int a_mt = r >> 4, a_g = r & 7, a_lr8 = (r >> 3) & 1;
    const int b_nt = r >> 3, b_g = r & 7;

    float4 pa[2], pb[2];
#pragma unroll
    for (int j = 0; j < 2; j++) {
        pa[j] = *(const float4*)&Arow[c0 + j * 4];
        pb[j] = *(const float4*)&Wrow[c0 + j * 4];
    }

    float acc[4][4][4];
#pragma unroll
    for (int mt = 0; mt < 4; mt++)
#pragma unroll
        for (int nt = 0; nt < 4; nt++)
#pragma unroll
            for (int x = 0; x < 4; x++) acc[mt][nt][x] = 0.f;

    // commit lambda-ish macro via inline code
#define COMMIT_STAGE(st)                                                        \
    {                                                                           \
        _Pragma("unroll")                                                       \
        for (int j = 0; j < 2; j++) {                                           \
            const int c   = c0 + j * 4;                                         \
            const int ks  = c >> 3;                                             \
            const int lk4 = (c >> 2) & 1;                                       \
            const int rgA = a_lr8 + 2 * lk4;                                    \
            unsigned* pA = &As[st][(((ks << 3) + a_mt) * 32 + a_g * 4) * 4 + rgA]; \
            pA[0]  = f2tf(pa[j].x); pA[4]  = f2tf(pa[j].y);                     \
            pA[8]  = f2tf(pa[j].z); pA[12] = f2tf(pa[j].w);                     \
            const int rgB = lk4;                                                \
            unsigned* pB = &Bs[st][(((ks << 4) + b_nt) * 32 + b_g * 4) * 2 + rgB]; \
            pB[0] = f2tf(pb[j].x); pB[2] = f2tf(pb[j].y);                       \
            pB[4] = f2tf(pb[j].z); pB[6] = f2tf(pb[j].w);                       \
        }                                                                       \
    }

    COMMIT_STAGE(0);
    __syncthreads();

    const int niters = K >> 4;
    for (int t = 0; t < niters; t++) {
        const int cur = t & 1;
        if (t + 1 < niters) {
            const int ko = (t + 1) * 16;
#pragma unroll
            for (int j = 0; j < 2; j++) {
                pa[j] = *(const float4*)&Arow[ko + c0 + j * 4];
                pb[j] = *(const float4*)&Wrow[ko + c0 + j * 4];
            }
        }

#pragma unroll
        for (int ks = 0; ks < 2; ks++) {
            unsigned af[4][4];
#pragma unroll
            for (int mt = 0; mt < 4; mt++) {
                const uint4 v = *(const uint4*)&As[cur][(((ks << 3) + wr * 4 + mt) * 32 + lane) * 4];
                af[mt][0] = v.x; af[mt][1] = v.y; af[mt][2] = v.z; af[mt][3] = v.w;
            }
            unsigned bf[4][2];
#pragma unroll
            for (int nt = 0; nt < 4; nt++) {
                const uint2 v = *(const uint2*)&Bs[cur][(((ks << 4) + wc * 4 + nt) * 32 + lane) * 2];
                bf[nt][0] = v.x; bf[nt][1] = v.y;
            }
#pragma unroll
            for (int mt = 0; mt < 4; mt++)
#pragma unroll
                for (int nt = 0; nt < 4; nt++)
                    mma8(acc[mt][nt], af[mt], bf[nt]);
        }

        if (t + 1 < niters) COMMIT_STAGE(cur ^ 1);
        __syncthreads();
    }
#undef COMMIT_STAGE

    // epilogue: bias + store (c-frag: rows g,g+8; cols qp*2,qp*2+1)
#pragma unroll
    for (int nt = 0; nt < 4; nt++) {
        const int cc = n0 + wc * 32 + nt * 8 + qp * 2;
        const float2 bb = *(const float2*)&bias[cc];
#pragma unroll
        for (int mt = 0; mt < 4; mt++) {
            const int rr = m0 + wr * 64 + mt * 16 + g;
            float2 v0, v1;
            v0.x = acc[mt][nt][0] + bb.x; v0.y = acc[mt][nt][1] + bb.y;
            v1.x = acc[mt][nt][2] + bb.x; v1.y = acc[mt][nt][3] + bb.y;
            *(float2*)&C[(size_t)rr * N + cc]       = v0;
            *(float2*)&C[(size_t)(rr + 8) * N + cc] = v1;
        }
    }
}

// ---------------------------------------------------------------------------
// Flash attention, tensor cores, frag-major smem, P via shuffles (no smem P).
// Block = (b, h, 128 q rows), 8 warps x 16 q rows, KV tiles of 64.
// Smem (words): Q 8192 (32KB) | K 4096 (16KB) | V 4096 (16KB) = 64KB dynamic.
// ---------------------------------------------------------------------------
__global__ __launch_bounds__(256, 2)
void attn_tc(const float* __restrict__ qkv, float* __restrict__ out)
{
    extern __shared__ unsigned sm[];
    unsigned* Qs = sm;           // frag (ks 0..7, wq 0..7): ((ks*8+wq)*32+lane)*4+reg
    unsigned* Ks = sm + 8192;    // frag (ks 0..7, nt 0..7): ((ks*8+nt)*32+lane)*2+reg
    unsigned* Vs = sm + 12288;   // frag (ks 0..7, nt 0..7): ((ks*8+nt)*32+lane)*2+reg

    const int tid  = threadIdx.x;
    const int lane = tid & 31;
    const int w    = tid >> 5;
    const int g    = lane >> 2;
    const int qp   = lane & 3;
    const int q0   = blockIdx.x * 128;
    const int h    = blockIdx.y;
    const int b    = blockIdx.z;

    const size_t base = (size_t)b * S_LEN * QKV_DIM + (size_t)h * (3 * D_HEAD);

    // ---- load Q tile into frag-major smem (scale + tf32) ----
#pragma unroll
    for (int i = 0; i < 8; i++) {
        const int lin = tid + i * 256;
        const int r   = lin >> 4;
        const int d4  = (lin & 15) * 4;
        const float4 q = *(const float4*)&qkv[base + (size_t)(q0 + r) * QKV_DIM + d4];
        const int ks  = d4 >> 3;
        const int reg = ((r >> 3) & 1) + 2 * ((d4 >> 2) & 1);
        unsigned* p = &Qs[(((ks << 3) + (r >> 4)) * 32 + (r & 7) * 4) * 4 + reg];
        p[0]  = f2tf(q.x * 0.125f); p[4]  = f2tf(q.y * 0.125f);
        p[8]  = f2tf(q.z * 0.125f); p[12] = f2tf(q.w * 0.125f);
    }

    float o[8][4];
#pragma unroll
    for (int nt = 0; nt < 8; nt++)
#pragma unroll
        for (int x = 0; x < 4; x++) o[nt][x] = 0.f;
    float m0v = -INFINITY, m1v = -INFINITY, l0 = 0.f, l1 = 0.f;

    const int psrc0 = (lane & ~3) | (qp >> 1);
    const int psrc1 = psrc0 + 2;
    const bool podd = qp & 1;

    for (int kt = 0; kt < S_LEN / 64; kt++) {
        __syncthreads();   // prior PV reads of Vs/Ks done
        const int j0 = kt * 64;
#pragma unroll
        for (int i = 0; i < 4; i++) {
            const int lin = tid + i * 256;
            const int r   = lin >> 4;
            const int d4  = (lin & 15) * 4;
            const size_t rb = base + (size_t)(j0 + r) * QKV_DIM + d4;
            const float4 kk = *(const float4*)&qkv[rb + D_HEAD];
            const float4 vv = *(const float4*)&qkv[rb + 2 * D_HEAD];
            // K frag: k-index = d, n-index = r
            {
                const int ks  = d4 >> 3;
                const int reg = (d4 >> 2) & 1;
                unsigned* p = &Ks[(((ks << 3) + (r >> 3)) * 32 + (r & 7) * 4) * 2 + reg];
                p[0] = f2tf(kk.x); p[2] = f2tf(kk.y);
                p[4] = f2tf(kk.z); p[6] = f2tf(kk.w);
            }
            // V frag: k-index = r, n-index = d
            {
                const int ks  = r >> 3;
                const int reg = (r >> 2) & 1;
                unsigned* p = &Vs[(((ks << 3) + (d4 >> 3)) * 32 + (d4 & 7) * 4 + (r & 3)) * 2 + reg];
                p[0]  = f2tf(vv.x); p[8]  = f2tf(vv.y);
                p[16] = f2tf(vv.z); p[24] = f2tf(vv.w);
            }
        }
        __syncthreads();

        // ---- S = Q @ K^T ----
        float s[8][4];
#pragma unroll
        for (int nt = 0; nt < 8; nt++)
#pragma unroll
            for (int x = 0; x < 4; x++) s[nt][x] = 0.f;

#pragma unroll
        for (int ks = 0; ks < 8; ks++) {
            const uint4 a4 = *(const uint4*)&Qs[(((ks << 3) + w) * 32 + lane) * 4];
            unsigned aq[4] = {a4.x, a4.y, a4.z, a4.w};
#pragma unroll
            for (int nt = 0; nt < 8; nt++) {
                const uint2 bv = *(const uint2*)&Ks[(((ks << 3) + nt) * 32 + lane) * 2];
                unsigned bk[2] = {bv.x, bv.y};
                mma8(s[nt], aq, bk);
            }
        }

        // ---- online softmax (rows g, g+8 of warp tile) ----
        float rm0 = s[0][0], rm1 = s[0][2];
#pragma unroll
        for (int nt = 0; nt < 8; nt++) {
            rm0 = fmaxf(rm0, fmaxf(s[nt][0], s[nt][1]));
            rm1 = fmaxf(rm1, fmaxf(s[nt][2], s[nt][3]));
        }
        rm0 = fmaxf(rm0, __shfl_xor_sync(0xffffffffu, rm0, 1));
        rm0 = fmaxf(rm0, __shfl_xor_sync(0xffffffffu, rm0, 2));
        rm1 = fmaxf(rm1, __shfl_xor_sync(0xffffffffu, rm1, 1));
        rm1 = fmaxf(rm1, __shfl_xor_sync(0xffffffffu, rm1, 2));

        const float mn0 = fmaxf(m0v, rm0);
        const float mn1 = fmaxf(m1v, rm1);
        const float corr0 = __expf(m0v - mn0);
        const float corr1 = __expf(m1v - mn1);
        m0v = mn0; m1v = mn1;

        float rs0 = 0.f, rs1 = 0.f;
#pragma unroll
        for (int nt = 0; nt < 8; nt++) {
            s[nt][0] = __expf(s[nt][0] - mn0);
            s[nt][1] = __expf(s[nt][1] - mn0);
            s[nt][2] = __expf(s[nt][2] - mn1);
            s[nt][3] = __expf(s[nt][3] - mn1);
            rs0 += s[nt][0] + s[nt][1];
            rs1 += s[nt][2] + s[nt][3];
        }
        rs0 += __shfl_xor_sync(0xffffffffu, rs0, 1);
        rs0 += __shfl_xor_sync(0xffffffffu, rs0, 2);
        rs1 += __shfl_xor_sync(0xffffffffu, rs1, 1);
        rs1 += __shfl_xor_sync(0xffffffffu, rs1, 2);
        l0 = l0 * corr0 + rs0;
        l1 = l1 * corr1 + rs1;

#pragma unroll
        for (int nt = 0; nt < 8; nt++) {
            o[nt][0] *= corr0; o[nt][1] *= corr0;
            o[nt][2] *= corr1; o[nt][3] *= corr1;
        }

        // ---- O += P @ V : C-frag -> A-frag via quad shuffles, no smem ----
#pragma unroll
        for (int nt = 0; nt < 8; nt++) {   // nt = k-step of PV (8 j-columns)
            const float x0 = __shfl_sync(0xffffffffu, s[nt][0], psrc0);
            const float x1 = __shfl_sync(0xffffffffu, s[nt][1], psrc0);
            const float x2 = __shfl_sync(0xffffffffu, s[nt][2], psrc0);
            const float x3 = __shfl_sync(0xffffffffu, s[nt][3], psrc0);
            const float y0 = __shfl_sync(0xffffffffu, s[nt][0], psrc1);
            const float y1 = __shfl_sync(0xffffffffu, s[nt][1], psrc1);
            const float y2 = __shfl_sync(0xffffffffu, s[nt][2], psrc1);
            const float y3 = __shfl_sync(0xffffffffu, s[nt][3], psrc1);
            unsigned ap[4];
            ap[0] = f2tf(podd ? x1 : x0);
            ap[1] = f2tf(podd ? x3 : x2);
            ap[2] = f2tf(podd ? y1 : y0);
            ap[3] = f2tf(podd ? y3 : y2);
#pragma unroll
            for (int nd = 0; nd < 8; nd++) {
                const uint2 bv = *(const uint2*)&Vs[(((nt << 3) + nd) * 32 + lane) * 2];
                unsigned bb[2] = {bv.x, bv.y};
                mma8(o[nd], ap, bb);
            }
        }
    }

    // ---- normalize + write [B,S,E] ----
    const float inv0 = 1.f / l0;
    const float inv1 = 1.f / l1;
    const int row0 = q0 + w * 16 + g;
#pragma unroll
    for (int nt = 0; nt < 8; nt++) {
        const int cc = h * D_HEAD + nt * 8 + qp * 2;
        float2 v0, v1;
        v0.x = o[nt][0] * inv0; v0.y = o[nt][1] * inv0;
        v1.x = o[nt][2] * inv1; v1.y = o[nt][3] * inv1;
        *(float2*)&out[((size_t)b * S_LEN + row0) * E_DIM + cc]     = v0;
        *(float2*)&out[((size_t)b * S_LEN + row0 + 8) * E_DIM + cc] = v1;
    }
}

// ---------------------------------------------------------------------------
extern "C" void kernel_launch(void* const* d_in, const int* in_sizes, int n_in,
                              void* d_out, int out_size)
{
    const float* x     = (const float*)d_in[0];
    const float* w_qkv = (const float*)d_in[1];
    const float* b_qkv = (const float*)d_in[2];
    const float* w_o   = (const float*)d_in[3];
    const float* b_o   = (const float*)d_in[4];
    float* out = (float*)d_out;

    float* qkv;  cudaGetSymbolAddress((void**)&qkv,  g_qkv);
    float* attn; cudaGetSymbolAddress((void**)&attn, g_attn);

    const int M = B_SZ * S_LEN;   // 4096

    // 1) QKV projection: [4096,1024] @ [3072,1024]^T
    gemm_tc<<<dim3(QKV_DIM / 128, M / 128), 256>>>(
        x, w_qkv, b_qkv, qkv, M, QKV_DIM, E_DIM);

    // 2) Flash attention
    const int attn_smem = 16384 * (int)sizeof(unsigned);   // 64 KB
    static int attr_set = 0;
    if (!attr_set) {
        cudaFuncSetAttribute(attn_tc,
                             cudaFuncAttributeMaxDynamicSharedMemorySize, attn_smem);
        attr_set = 1;
    }
    attn_tc<<<dim3(S_LEN / 128, H_NUM, B_SZ), 256, attn_smem>>>(qkv, attn);

    // 3) Output projection: [4096,1024] @ [1024,1024]^T
    gemm_tc<<<dim3(E_DIM / 128, M / 128), 256>>>(
        attn, w_o, b_o, out, M, E_DIM, E_DIM);
}

// round 5
// speedup vs baseline: 1.6697x; 1.6697x over previous
#include <cuda_runtime.h>
#include <math.h>

#define B_SZ   2
#define S_LEN  2048
#define E_DIM  1024
#define H_NUM  16
#define D_HEAD 64
#define QKV_DIM 3072   // 3 * E_DIM

// Scratch (allocation-free rule: device globals)
__device__ float g_qkv[B_SZ * S_LEN * QKV_DIM];   // [B,S,3E]
__device__ float g_attn[B_SZ * S_LEN * E_DIM];    // [B,S,E]

// ---------------------------------------------------------------------------
// helpers
// ---------------------------------------------------------------------------
__device__ __forceinline__ unsigned f2tf(float f) {
    unsigned u;
    asm("cvt.rna.tf32.f32 %0, %1;" : "=r"(u) : "f"(f));
    return u;
}

// D += A(16x8 tf32 row) * B(8x8 tf32 col), fp32 accumulate, in-place
__device__ __forceinline__ void mma8(float* d, const unsigned* a, const unsigned* b) {
    asm volatile(
        "mma.sync.aligned.m16n8k8.row.col.f32.tf32.tf32.f32 "
        "{%0,%1,%2,%3},{%4,%5,%6,%7},{%8,%9},{%0,%1,%2,%3};"
        : "+f"(d[0]), "+f"(d[1]), "+f"(d[2]), "+f"(d[3])
        : "r"(a[0]), "r"(a[1]), "r"(a[2]), "r"(a[3]), "r"(b[0]), "r"(b[1]));
}

__device__ __forceinline__ void cpa16(const void* smem_dst, const void* gmem_src) {
    unsigned a = (unsigned)__cvta_generic_to_shared(smem_dst);
    asm volatile("cp.async.cg.shared.global [%0], [%1], 16;" :: "r"(a), "l"(gmem_src));
}
#define CP_COMMIT() asm volatile("cp.async.commit_group;")
#define CP_WAIT0()  asm volatile("cp.async.wait_group 0;")

// ---------------------------------------------------------------------------
// Tensor-core GEMM: C[M,N] = A[M,K] @ W[N,K]^T + bias[N]
// 128x128x32 tiles, 8 warps, warp tile 64x32 (4x4 m16n8k8).
// fp32 smem (GS=36, conflict-free), cp.async 2-stage, cvt at frag load.
// smem = 2 stages * 2 matrices * 128*36 words = 73728 B (dynamic).
// ---------------------------------------------------------------------------
#define GS 36
#define GSTAGE (128 * GS)   // 4608 words per matrix per stage

__global__ __launch_bounds__(256, 2)
void gemm_tc(const float* __restrict__ A, const float* __restrict__ W,
             const float* __restrict__ bias, float* __restrict__ C,
             int M, int N, int K)
{
    extern __shared__ float gsm[];   // [2][A:GSTAGE | B:GSTAGE]

    const int tid  = threadIdx.x;
    const int lane = tid & 31;
    const int w    = tid >> 5;
    const int wr   = w >> 2;     // 0..1
    const int wc   = w & 3;      // 0..3
    const int g    = lane >> 2;
    const int qp   = lane & 3;
    const int m0   = blockIdx.y * 128;
    const int n0   = blockIdx.x * 128;

    auto issue = [&](int t) {
        const int k0 = t * 32;
        float* dst = &gsm[(t & 1) * 2 * GSTAGE];
#pragma unroll
        for (int i = 0; i < 4; i++) {
            const int lin = tid + i * 256;
            const int r   = lin >> 3;          // 0..127
            const int c4  = (lin & 7) * 4;     // 0..28
            cpa16(&dst[r * GS + c4],          &A[(size_t)(m0 + r) * K + k0 + c4]);
            cpa16(&dst[GSTAGE + r * GS + c4], &W[(size_t)(n0 + r) * K + k0 + c4]);
        }
        CP_COMMIT();
    };

    float acc[4][4][4];
#pragma unroll
    for (int mt = 0; mt < 4; mt++)
#pragma unroll
        for (int nt = 0; nt < 4; nt++)
#pragma unroll
            for (int x = 0; x < 4; x++) acc[mt][nt][x] = 0.f;

    issue(0);

    const int niters = K >> 5;
    for (int t = 0; t < niters; t++) {
        CP_WAIT0();            // stage t data arrived (this thread)
        __syncthreads();       // all threads' stage t arrived; compute(t-1) done
        if (t + 1 < niters) issue(t + 1);   // overlaps compute(t)

        const float* As = &gsm[(t & 1) * 2 * GSTAGE];
        const float* Bs = As + GSTAGE;

#pragma unroll
        for (int ks = 0; ks < 4; ks++) {
            const int kb = ks * 8;
            unsigned af[4][4];
#pragma unroll
            for (int mt = 0; mt < 4; mt++) {
                const int r0 = (wr * 64 + mt * 16 + g) * GS + kb + qp;
                af[mt][0] = f2tf(As[r0]);
                af[mt][1] = f2tf(As[r0 + 8 * GS]);
                af[mt][2] = f2tf(As[r0 + 4]);
                af[mt][3] = f2tf(As[r0 + 8 * GS + 4]);
            }
            unsigned bf[4][2];
#pragma unroll
            for (int nt = 0; nt < 4; nt++) {
                const int c0 = (wc * 32 + nt * 8 + g) * GS + kb + qp;
                bf[nt][0] = f2tf(Bs[c0]);
                bf[nt][1] = f2tf(Bs[c0 + 4]);
            }
#pragma unroll
            for (int mt = 0; mt < 4; mt++)
#pragma unroll
                for (int nt = 0; nt < 4; nt++)
                    mma8(acc[mt][nt], af[mt], bf[nt]);
        }
    }

    // epilogue: bias + store (c-frag: rows g,g+8; cols qp*2,qp*2+1)
#pragma unroll
    for (int nt = 0; nt < 4; nt++) {
        const int cc = n0 + wc * 32 + nt * 8 + qp * 2;
        const float2 bb = *(const float2*)&bias[cc];
#pragma unroll
        for (int mt = 0; mt < 4; mt++) {
            const int rr = m0 + wr * 64 + mt * 16 + g;
            float2 v0, v1;
            v0.x = acc[mt][nt][0] + bb.x; v0.y = acc[mt][nt][1] + bb.y;
            v1.x = acc[mt][nt][2] + bb.x; v1.y = acc[mt][nt][3] + bb.y;
            *(float2*)&C[(size_t)rr * N + cc]       = v0;
            *(float2*)&C[(size_t)(rr + 8) * N + cc] = v1;
        }
    }
}

// ---------------------------------------------------------------------------
// Flash attention, tensor cores.
// Block = (b, h, 128 q rows), 8 warps x 16 q rows, KV tiles of 64.
// Q staged once (tf32, stride 68). K/V cp.async double-buffered (fp32,
// strides 68/72 -> conflict-free scalar frag loads), cvt at frag load.
// P transposed C-frag -> A-frag via quad shuffles (no smem P, no extra sync).
// smem words: Q 128*68 = 8704 | 2 * (64*68 + 64*72) = 17920  -> 106496 B.
// ---------------------------------------------------------------------------
#define AQ 68
#define AK 68
#define AV 72
#define KV_STAGE (64 * AK + 64 * AV)            // 8960 words
#define ATTN_SMEM_W (128 * AQ + 2 * KV_STAGE)   // 26624 words

__global__ __launch_bounds__(256, 2)
void attn_tc(const float* __restrict__ qkv, float* __restrict__ out)
{
    extern __shared__ unsigned smu[];

    const int tid  = threadIdx.x;
    const int lane = tid & 31;
    const int w    = tid >> 5;
    const int g    = lane >> 2;
    const int qp   = lane & 3;
    const int q0   = blockIdx.x * 128;
    const int h    = blockIdx.y;
    const int b    = blockIdx.z;

    const size_t base = (size_t)b * S_LEN * QKV_DIM + (size_t)h * (3 * D_HEAD);

    auto issue_kv = [&](int kt) {
        const int j0  = kt * 64;
        const int off = 128 * AQ + (kt & 1) * KV_STAGE;
#pragma unroll
        for (int i = 0; i < 4; i++) {
            const int lin = tid + i * 256;
            const int j   = lin >> 4;          // 0..63
            const int c4  = (lin & 15) * 4;    // 0..60
            const float* src = &qkv[base + (size_t)(j0 + j) * QKV_DIM + c4];
            cpa16(&smu[off + j * AK + c4],           src + D_HEAD);       // K
            cpa16(&smu[off + 64 * AK + j * AV + c4], src + 2 * D_HEAD);   // V
        }
        CP_COMMIT();
    };

    // ---- stage Q (scaled, tf32) + kick off first K/V tile ----
#pragma unroll
    for (int i = 0; i < 8; i++) {
        const int lin = tid + i * 256;
        const int r   = lin >> 4;
        const int d4  = (lin & 15) * 4;
        const float4 q = *(const float4*)&qkv[base + (size_t)(q0 + r) * QKV_DIM + d4];
        uint4 u;
        u.x = f2tf(q.x * 0.125f); u.y = f2tf(q.y * 0.125f);
        u.z = f2tf(q.z * 0.125f); u.w = f2tf(q.w * 0.125f);
        *(uint4*)&smu[r * AQ + d4] = u;
    }
    issue_kv(0);

    float o[8][4];
#pragma unroll
    for (int nt = 0; nt < 8; nt++)
#pragma unroll
        for (int x = 0; x < 4; x++) o[nt][x] = 0.f;
    float m0v = -INFINITY, m1v = -INFINITY, l0 = 0.f, l1 = 0.f;

    const int pr0   = w * 16 + g;
    const int psrc0 = (lane & ~3) | (qp >> 1);
    const int psrc1 = psrc0 + 2;
    const bool podd = qp & 1;

    for (int kt = 0; kt < S_LEN / 64; kt++) {
        CP_WAIT0();            // K/V tile kt arrived (this thread)
        __syncthreads();       // everyone's tile kt arrived; compute(kt-1) done
        if (kt + 1 < S_LEN / 64) issue_kv(kt + 1);   // overlaps compute(kt)

        const int off = 128 * AQ + (kt & 1) * KV_STAGE;
        const float* Kf = (const float*)&smu[off];
        const float* Vf = (const float*)&smu[off + 64 * AK];

        // ---- S = Q @ K^T ----
        float s[8][4];
#pragma unroll
        for (int nt = 0; nt < 8; nt++)
#pragma unroll
            for (int x = 0; x < 4; x++) s[nt][x] = 0.f;

#pragma unroll
        for (int ks = 0; ks < 8; ks++) {
            const int kb = ks * 8;
            unsigned aq[4];
            aq[0] = smu[pr0 * AQ + kb + qp];
            aq[1] = smu[(pr0 + 8) * AQ + kb + qp];
            aq[2] = smu[pr0 * AQ + kb + qp + 4];
            aq[3] = smu[(pr0 + 8) * AQ + kb + qp + 4];
#pragma unroll
            for (int nt = 0; nt < 8; nt++) {
                const int c0 = (nt * 8 + g) * AK + kb + qp;
                unsigned bk[2];
                bk[0] = f2tf(Kf[c0]);
                bk[1] = f2tf(Kf[c0 + 4]);
                mma8(s[nt], aq, bk);
            }
        }

        // ---- online softmax (rows g, g+8 of warp tile) ----
        float rm0 = s[0][0], rm1 = s[0][2];
#pragma unroll
        for (int nt = 0; nt < 8; nt++) {
            rm0 = fmaxf(rm0, fmaxf(s[nt][0], s[nt][1]));
            rm1 = fmaxf(rm1, fmaxf(s[nt][2], s[nt][3]));
        }
        rm0 = fmaxf(rm0, __shfl_xor_sync(0xffffffffu, rm0, 1));
        rm0 = fmaxf(rm0, __shfl_xor_sync(0xffffffffu, rm0, 2));
        rm1 = fmaxf(rm1, __shfl_xor_sync(0xffffffffu, rm1, 1));
        rm1 = fmaxf(rm1, __shfl_xor_sync(0xffffffffu, rm1, 2));

        const float mn0 = fmaxf(m0v, rm0);
        const float mn1 = fmaxf(m1v, rm1);
        const float corr0 = __expf(m0v - mn0);
        const float corr1 = __expf(m1v - mn1);
        m0v = mn0; m1v = mn1;

        float rs0 = 0.f, rs1 = 0.f;
#pragma unroll
        for (int nt = 0; nt < 8; nt++) {
            s[nt][0] = __expf(s[nt][0] - mn0);
            s[nt][1] = __expf(s[nt][1] - mn0);
            s[nt][2] = __expf(s[nt][2] - mn1);
            s[nt][3] = __expf(s[nt][3] - mn1);
            rs0 += s[nt][0] + s[nt][1];
            rs1 += s[nt][2] + s[nt][3];
        }
        rs0 += __shfl_xor_sync(0xffffffffu, rs0, 1);
        rs0 += __shfl_xor_sync(0xffffffffu, rs0, 2);
        rs1 += __shfl_xor_sync(0xffffffffu, rs1, 1);
        rs1 += __shfl_xor_sync(0xffffffffu, rs1, 2);
        l0 = l0 * corr0 + rs0;
        l1 = l1 * corr1 + rs1;

#pragma unroll
        for (int nt = 0; nt < 8; nt++) {
            o[nt][0] *= corr0; o[nt][1] *= corr0;
            o[nt][2] *= corr1; o[nt][3] *= corr1;
        }

        // ---- O += P @ V : C-frag -> A-frag via quad shuffles ----
#pragma unroll
        for (int nt = 0; nt < 8; nt++) {   // nt = k-step of PV (8 j-columns)
            const float x0 = __shfl_sync(0xffffffffu, s[nt][0], psrc0);
            const float x1 = __shfl_sync(0xffffffffu, s[nt][1], psrc0);
            const float x2 = __shfl_sync(0xffffffffu, s[nt][2], psrc0);
            const float x3 = __shfl_sync(0xffffffffu, s[nt][3], psrc0);
            const float y0 = __shfl_sync(0xffffffffu, s[nt][0], psrc1);
            const float y1 = __shfl_sync(0xffffffffu, s[nt][1], psrc1);
            const float y2 = __shfl_sync(0xffffffffu, s[nt][2], psrc1);
            const float y3 = __shfl_sync(0xffffffffu, s[nt][3], psrc1);
            unsigned ap[4];
            ap[0] = f2tf(podd ? x1 : x0);
            ap[1] = f2tf(podd ? x3 : x2);
            ap[2] = f2tf(podd ? y1 : y0);
            ap[3] = f2tf(podd ? y3 : y2);
#pragma unroll
            for (int nd = 0; nd < 8; nd++) {
                unsigned bb[2];
                bb[0] = f2tf(Vf[(nt * 8 + qp) * AV + nd * 8 + g]);
                bb[1] = f2tf(Vf[(nt * 8 + qp + 4) * AV + nd * 8 + g]);
                mma8(o[nd], ap, bb);
            }
        }
    }

    // ---- normalize + write [B,S,E] ----
    const float inv0 = 1.f / l0;
    const float inv1 = 1.f / l1;
    const int row0 = q0 + w * 16 + g;
#pragma unroll
    for (int nt = 0; nt < 8; nt++) {
        const int cc = h * D_HEAD + nt * 8 + qp * 2;
        float2 v0, v1;
        v0.x = o[nt][0] * inv0; v0.y = o[nt][1] * inv0;
        v1.x = o[nt][2] * inv1; v1.y = o[nt][3] * inv1;
        *(float2*)&out[((size_t)b * S_LEN + row0) * E_DIM + cc]     = v0;
        *(float2*)&out[((size_t)b * S_LEN + row0 + 8) * E_DIM + cc] = v1;
    }
}

// ---------------------------------------------------------------------------
extern "C" void kernel_launch(void* const* d_in, const int* in_sizes, int n_in,
                              void* d_out, int out_size)
{
    const float* x     = (const float*)d_in[0];
    const float* w_qkv = (const float*)d_in[1];
    const float* b_qkv = (const float*)d_in[2];
    const float* w_o   = (const float*)d_in[3];
    const float* b_o   = (const float*)d_in[4];
    float* out = (float*)d_out;

    float* qkv;  cudaGetSymbolAddress((void**)&qkv,  g_qkv);
    float* attn; cudaGetSymbolAddress((void**)&attn, g_attn);

    const int M = B_SZ * S_LEN;   // 4096
    const int gemm_smem = 4 * GSTAGE * (int)sizeof(float);        // 73728
    const int attn_smem = ATTN_SMEM_W * (int)sizeof(unsigned);    // 106496

    static int attr_set = 0;
    if (!attr_set) {
        cudaFuncSetAttribute(gemm_tc,
                             cudaFuncAttributeMaxDynamicSharedMemorySize, gemm_smem);
        cudaFuncSetAttribute(attn_tc,
                             cudaFuncAttributeMaxDynamicSharedMemorySize, attn_smem);
        attr_set = 1;
    }

    // 1) QKV projection: [4096,1024] @ [3072,1024]^T
    gemm_tc<<<dim3(QKV_DIM / 128, M / 128), 256, gemm_smem>>>(
        x, w_qkv, b_qkv, qkv, M, QKV_DIM, E_DIM);

    // 2) Flash attention
    attn_tc<<<dim3(S_LEN / 128, H_NUM, B_SZ), 256, attn_smem>>>(qkv, attn);

    // 3) Output projection: [4096,1024] @ [1024,1024]^T
    gemm_tc<<<dim3(E_DIM / 128, M / 128), 256, gemm_smem>>>(
        attn, w_o, b_o, out, M, E_DIM, E_DIM);
}

// round 7
// speedup vs baseline: 1.9612x; 1.1746x over previous
#include <cuda_runtime.h>
#include <math.h>

#define B_SZ   2
#define S_LEN  2048
#define E_DIM  1024
#define H_NUM  16
#define D_HEAD 64
#define QKV_DIM 3072   // 3 * E_DIM

// Scratch (allocation-free rule: device globals)
__device__ float g_qkv[B_SZ * S_LEN * QKV_DIM];   // [B,S,3E] tf32 bits, q/k d-permuted
__device__ float g_attn[B_SZ * S_LEN * E_DIM];    // [B,S,E]  tf32 bits, k-permuted
__device__ float g_xp[B_SZ * S_LEN * E_DIM];      // x, tf32 bits, k-permuted
__device__ float g_wqkvp[QKV_DIM * E_DIM];        // w_qkv, tf32 bits, k-permuted
__device__ float g_wop[E_DIM * E_DIM];            // w_o, tf32 bits, k-permuted

// ---------------------------------------------------------------------------
// helpers
// ---------------------------------------------------------------------------
__device__ __forceinline__ unsigned f2tf(float f) {
    unsigned u;
    asm("cvt.rna.tf32.f32 %0, %1;" : "=r"(u) : "f"(f));
    return u;
}
__device__ __forceinline__ float tfbits(float f) { return __uint_as_float(f2tf(f)); }

// D += A(16x8 tf32 row) * B(8x8 tf32 col), fp32 accumulate, in-place
__device__ __forceinline__ void mma8(float* d, const unsigned* a, const unsigned* b) {
    asm volatile(
        "mma.sync.aligned.m16n8k8.row.col.f32.tf32.tf32.f32 "
        "{%0,%1,%2,%3},{%4,%5,%6,%7},{%8,%9},{%0,%1,%2,%3};"
        : "+f"(d[0]), "+f"(d[1]), "+f"(d[2]), "+f"(d[3])
        : "r"(a[0]), "r"(a[1]), "r"(a[2]), "r"(a[3]), "r"(b[0]), "r"(b[1]));
}

__device__ __forceinline__ void cpa16(const void* smem_dst, const void* gmem_src) {
    unsigned a = (unsigned)__cvta_generic_to_shared(smem_dst);
    asm volatile("cp.async.cg.shared.global [%0], [%1], 16;" :: "r"(a), "l"(gmem_src));
}
#define CP_COMMIT() asm volatile("cp.async.commit_group;")
#define CP_WAIT0()  asm volatile("cp.async.wait_group 0;")

// ---------------------------------------------------------------------------
// Pre-pass: fp32 -> tf32 bits, permute each 8-group of the contiguous (K) dim
// as [0,4,1,5,2,6,3,7] so MMA k-pairs (qp, qp+4) become physically adjacent.
// ---------------------------------------------------------------------------
__global__ void prep_tf32(const float* __restrict__ src, float* __restrict__ dst,
                          int ngroups)
{
    const int i = blockIdx.x * blockDim.x + threadIdx.x;
    if (i >= ngroups) return;
    const float4 a = *(const float4*)&src[(size_t)i * 8];
    const float4 b = *(const float4*)&src[(size_t)i * 8 + 4];
    float4 o0, o1;
    o0.x = tfbits(a.x); o0.y = tfbits(b.x); o0.z = tfbits(a.y); o0.w = tfbits(b.y);
    o1.x = tfbits(a.z); o1.y = tfbits(b.z); o1.z = tfbits(a.w); o1.w = tfbits(b.w);
    *(float4*)&dst[(size_t)i * 8]     = o0;
    *(float4*)&dst[(size_t)i * 8 + 4] = o1;
}

// ---------------------------------------------------------------------------
// Tensor-core GEMM: C[M,N] = A[M,K] @ W[N,K]^T + bias[N]
// A, W already tf32 bits with permuted K. 128x128x32 tiles, 8 warps,
// warp tile 64x32. cp.async 2-stage, LDS.64 frag loads, no inner-loop cvt.
// MODE 0: output fp32 identity (final). MODE 1: output tf32 bits; q/k head
// sections (col%192 < 128) permuted in their 8-group, v identity.
// ---------------------------------------------------------------------------
#define GS 40                 // 40 mod 32 == 8 -> conflict-free LDS.64 phases
#define GSTAGE (128 * GS)     // 5120 words per matrix per stage

template<int MODE>
__global__ __launch_bounds__(256, 2)
void gemm_tc(const float* __restrict__ A, const float* __restrict__ W,
             const float* __restrict__ bias, float* __restrict__ C,
             int M, int N, int K)
{
    extern __shared__ unsigned gsm[];   // [2][A:GSTAGE | B:GSTAGE]

    const int tid  = threadIdx.x;
    const int lane = tid & 31;
    const int w    = tid >> 5;
    const int wr   = w >> 2;     // 0..1
    const int wc   = w & 3;      // 0..3
    const int g    = lane >> 2;
    const int qp   = lane & 3;
    const int m0   = blockIdx.y * 128;
    const int n0   = blockIdx.x * 128;

    auto issue = [&](int t) {
        const int k0 = t * 32;
        unsigned* dst = &gsm[(t & 1) * 2 * GSTAGE];
#pragma unroll
        for (int i = 0; i < 4; i++) {
            const int lin = tid + i * 256;
            const int r   = lin >> 3;          // 0..127
            const int c4  = (lin & 7) * 4;     // 0..28
            cpa16(&dst[r * GS + c4],          &A[(size_t)(m0 + r) * K + k0 + c4]);
            cpa16(&dst[GSTAGE + r * GS + c4], &W[(size_t)(n0 + r) * K + k0 + c4]);
        }
        CP_COMMIT();
    };

    float acc[4][4][4];
#pragma unroll
    for (int mt = 0; mt < 4; mt++)
#pragma unroll
        for (int nt = 0; nt < 4; nt++)
#pragma unroll
            for (int x = 0; x < 4; x++) acc[mt][nt][x] = 0.f;

    issue(0);

    const int niters = K >> 5;
    for (int t = 0; t < niters; t++) {
        CP_WAIT0();
        __syncthreads();
        if (t + 1 < niters) issue(t + 1);

        const unsigned* As = &gsm[(t & 1) * 2 * GSTAGE];
        const unsigned* Bs = As + GSTAGE;

#pragma unroll
        for (int ks = 0; ks < 4; ks++) {
            const int kb = ks * 8;
            unsigned af[4][4];
#pragma unroll
            for (int mt = 0; mt < 4; mt++) {
                const int r0 = (wr * 64 + mt * 16 + g) * GS + kb + 2 * qp;
                const uint2 u0 = *(const uint2*)&As[r0];
                const uint2 u1 = *(const uint2*)&As[r0 + 8 * GS];
                af[mt][0] = u0.x; af[mt][1] = u1.x;
                af[mt][2] = u0.y; af[mt][3] = u1.y;
            }
            unsigned bf[4][2];
#pragma unroll
            for (int nt = 0; nt < 4; nt++) {
                const uint2 v = *(const uint2*)&Bs[(wc * 32 + nt * 8 + g) * GS + kb + 2 * qp];
                bf[nt][0] = v.x; bf[nt][1] = v.y;
            }
#pragma unroll
            for (int mt = 0; mt < 4; mt++)
#pragma unroll
                for (int nt = 0; nt < 4; nt++)
                    mma8(acc[mt][nt], af[mt], bf[nt]);
        }
    }

    // epilogue (c-frag: rows g,g+8; logical cols qp*2, qp*2+1)
    const int p0 = (qp & 1) * 4 + (qp >> 1);   // physical slot of logical 2qp
#pragma unroll
    for (int nt = 0; nt < 4; nt++) {
        const int cb = n0 + wc * 32 + nt * 8;      // 8-group base
        const float2 bb = *(const float2*)&bias[cb + qp * 2];
#pragma unroll
        for (int mt = 0; mt < 4; mt++) {
            const int rr = m0 + wr * 64 + mt * 16 + g;
            const float v00 = acc[mt][nt][0] + bb.x;
            const float v01 = acc[mt][nt][1] + bb.y;
            const float v10 = acc[mt][nt][2] + bb.x;
            const float v11 = acc[mt][nt][3] + bb.y;
            if (MODE == 0) {
                *(float2*)&C[(size_t)rr * N + cb + qp * 2]       = make_float2(v00, v01);
                *(float2*)&C[(size_t)(rr + 8) * N + cb + qp * 2] = make_float2(v10, v11);
            } else {
                const bool perm = (cb % 192) < 128;   // q/k head-dim sections
                if (perm) {
                    C[(size_t)rr * N + cb + p0]           = tfbits(v00);
                    C[(size_t)rr * N + cb + p0 + 2]       = tfbits(v01);
                    C[(size_t)(rr + 8) * N + cb + p0]     = tfbits(v10);
                    C[(size_t)(rr + 8) * N + cb + p0 + 2] = tfbits(v11);
                } else {
                    *(float2*)&C[(size_t)rr * N + cb + qp * 2] =
                        make_float2(tfbits(v00), tfbits(v01));
                    *(float2*)&C[(size_t)(rr + 8) * N + cb + qp * 2] =
                        make_float2(tfbits(v10), tfbits(v11));
                }
            }
        }
    }
}

// ---------------------------------------------------------------------------
// Flash attention, tensor cores. qkv holds tf32 bits; q/k sections permuted
// in d (so Q/K frags are LDS.64), v identity. Output: tf32 bits, permuted
// (feeds O-proj). No cvt in QK/PV except P after exp.
// ---------------------------------------------------------------------------
#define AQ 72
#define AK 72
#define AV 72
#define KV_STAGE (64 * AK + 64 * AV)            // 9216 words
#define ATTN_SMEM_W (128 * AQ + 2 * KV_STAGE)   // 27648 words = 110592 B

__global__ __launch_bounds__(256, 2)
void attn_tc(const float* __restrict__ qkv, float* __restrict__ out)
{
    extern __shared__ unsigned smu[];

    const int tid  = threadIdx.x;
    const int lane = tid & 31;
    const int w    = tid >> 5;
    const int g    = lane >> 2;
    const int qp   = lane & 3;
    const int q0   = blockIdx.x * 128;
    const int h    = blockIdx.y;
    const int b    = blockIdx.z;

    const size_t base = (size_t)b * S_LEN * QKV_DIM + (size_t)h * (3 * D_HEAD);

    auto issue_kv = [&](int kt) {
        const int j0  = kt * 64;
        const int off = 128 * AQ + (kt & 1) * KV_STAGE;
#pragma unroll
        for (int i = 0; i < 4; i++) {
            const int lin = tid + i * 256;
            const int j   = lin >> 4;          // 0..63
            const int c4  = (lin & 15) * 4;    // 0..60
            const float* src = &qkv[base + (size_t)(j0 + j) * QKV_DIM + c4];
            cpa16(&smu[off + j * AK + c4],           src + D_HEAD);       // K (perm)
            cpa16(&smu[off + 64 * AK + j * AV + c4], src + 2 * D_HEAD);   // V (id)
        }
        CP_COMMIT();
    };

    // ---- stage Q (tf32 bits already; *0.125 is exact on tf32) ----
#pragma unroll
    for (int i = 0; i < 8; i++) {
        const int lin = tid + i * 256;
        const int r   = lin >> 4;
        const int d4  = (lin & 15) * 4;
        const float4 q = *(const float4*)&qkv[base + (size_t)(q0 + r) * QKV_DIM + d4];
        uint4 u;
        u.x = __float_as_uint(q.x * 0.125f); u.y = __float_as_uint(q.y * 0.125f);
        u.z = __float_as_uint(q.z * 0.125f); u.w = __float_as_uint(q.w * 0.125f);
        *(uint4*)&smu[r * AQ + d4] = u;
    }
    issue_kv(0);

    float o[8][4];
#pragma unroll
    for (int nt = 0; nt < 8; nt++)
#pragma unroll
        for (int x = 0; x < 4; x++) o[nt][x] = 0.f;
    float m0v = -INFINITY, m1v = -INFINITY, l0 = 0.f, l1 = 0.f;

    const int pr0   = w * 16 + g;
    const int psrc0 = (lane & ~3) | (qp >> 1);
    const int psrc1 = psrc0 + 2;
    const bool podd = qp & 1;

    for (int kt = 0; kt < S_LEN / 64; kt++) {
        CP_WAIT0();
        __syncthreads();
        if (kt + 1 < S_LEN / 64) issue_kv(kt + 1);

        const int off = 128 * AQ + (kt & 1) * KV_STAGE;
        const unsigned* Kf = &smu[off];
        const unsigned* Vf = &smu[off + 64 * AK];

        // ---- S = Q @ K^T (LDS.64 frags, no cvt) ----
        float s[8][4];
#pragma unroll
        for (int nt = 0; nt < 8; nt++)
#pragma unroll
            for (int x = 0; x < 4; x++) s[nt][x] = 0.f;

#pragma unroll
        for (int ks = 0; ks < 8; ks++) {
            const int kb = ks * 8;
            const int r0 = pr0 * AQ + kb + 2 * qp;
            const uint2 u0 = *(const uint2*)&smu[r0];
            const uint2 u1 = *(const uint2*)&smu[r0 + 8 * AQ];
            unsigned aq[4] = {u0.x, u1.x, u0.y, u1.y};
#pragma unroll
            for (int nt = 0; nt < 8; nt++) {
                const uint2 v = *(const uint2*)&Kf[(nt * 8 + g) * AK + kb + 2 * qp];
                unsigned bk[2] = {v.x, v.y};
                mma8(s[nt], aq, bk);
            }
        }

        // ---- online softmax (rows g, g+8 of warp tile) ----
        float rm0 = s[0][0], rm1 = s[0][2];
#pragma unroll
        for (int nt = 0; nt < 8; nt++) {
            rm0 = fmaxf(rm0, fmaxf(s[nt][0], s[nt][1]));
            rm1 = fmaxf(rm1, fmaxf(s[nt][2], s[nt][3]));
        }
        rm0 = fmaxf(rm0, __shfl_xor_sync(0xffffffffu, rm0, 1));
        rm0 = fmaxf(rm0, __shfl_xor_sync(0xffffffffu, rm0, 2));
        rm1 = fmaxf(rm1, __shfl_xor_sync(0xffffffffu, rm1, 1));
        rm1 = fmaxf(rm1, __shfl_xor_sync(0xffffffffu, rm1, 2));

        const float mn0 = fmaxf(m0v, rm0);
        const float mn1 = fmaxf(m1v, rm1);
        const float corr0 = __expf(m0v - mn0);
        const float corr1 = __expf(m1v - mn1);
        m0v = mn0; m1v = mn1;

        float rs0 = 0.f, rs1 = 0.f;
#pragma unroll
        for (int nt = 0; nt < 8; nt++) {
            s[nt][0] = __expf(s[nt][0] - mn0);
            s[nt][1] = __expf(s[nt][1] - mn0);
            s[nt][2] = __expf(s[nt][2] - mn1);
            s[nt][3] = __expf(s[nt][3] - mn1);
            rs0 += s[nt][0] + s[nt][1];
            rs1 += s[nt][2] + s[nt][3];
        }
        rs0 += __shfl_xor_sync(0xffffffffu, rs0, 1);
        rs0 += __shfl_xor_sync(0xffffffffu, rs0, 2);
        rs1 += __shfl_xor_sync(0xffffffffu, rs1, 1);
        rs1 += __shfl_xor_sync(0xffffffffu, rs1, 2);
        l0 = l0 * corr0 + rs0;
        l1 = l1 * corr1 + rs1;

#pragma unroll
        for (int nt = 0; nt < 8; nt++) {
            o[nt][0] *= corr0; o[nt][1] *= corr0;
            o[nt][2] *= corr1; o[nt][3] *= corr1;
        }

        // ---- O += P @ V : C-frag -> A-frag via quad shuffles ----
#pragma unroll
        for (int nt = 0; nt < 8; nt++) {   // nt = k-step of PV (8 j-columns)
            const float x0 = __shfl_sync(0xffffffffu, s[nt][0], psrc0);
            const float x1 = __shfl_sync(0xffffffffu, s[nt][1], psrc0);
            const float x2 = __shfl_sync(0xffffffffu, s[nt][2], psrc0);
            const float x3 = __shfl_sync(0xffffffffu, s[nt][3], psrc0);
            const float y0 = __shfl_sync(0xffffffffu, s[nt][0], psrc1);
            const float y1 = __shfl_sync(0xffffffffu, s[nt][1], psrc1);
            const float y2 = __shfl_sync(0xffffffffu, s[nt][2], psrc1);
            const float y3 = __shfl_sync(0xffffffffu, s[nt][3], psrc1);
            unsigned ap[4];
            ap[0] = f2tf(podd ? x1 : x0);
            ap[1] = f2tf(podd ? x3 : x2);
            ap[2] = f2tf(podd ? y1 : y0);
            ap[3] = f2tf(podd ? y3 : y2);
#pragma unroll
            for (int nd = 0; nd < 8; nd++) {
                unsigned bb[2];
                bb[0] = Vf[(nt * 8 + qp) * AV + nd * 8 + g];
                bb[1] = Vf[(nt * 8 + qp + 4) * AV + nd * 8 + g];
                mma8(o[nd], ap, bb);
            }
        }
    }

    // ---- normalize + write tf32 bits, k-permuted (feeds O-proj) ----
    const float inv0 = 1.f / l0;
    const float inv1 = 1.f / l1;
    const int row0 = q0 + w * 16 + g;
    const int p0 = (qp & 1) * 4 + (qp >> 1);
#pragma unroll
    for (int nt = 0; nt < 8; nt++) {
        const int cb = h * D_HEAD + nt * 8;
        float* r0p = &out[((size_t)b * S_LEN + row0) * E_DIM + cb];
        float* r1p = &out[((size_t)b * S_LEN + row0 + 8) * E_DIM + cb];
        r0p[p0]     = tfbits(o[nt][0] * inv0);
        r0p[p0 + 2] = tfbits(o[nt][1] * inv0);
        r1p[p0]     = tfbits(o[nt][2] * inv1);
        r1p[p0 + 2] = tfbits(o[nt][3] * inv1);
    }
}

// ---------------------------------------------------------------------------
extern "C" void kernel_launch(void* const* d_in, const int* in_sizes, int n_in,
                              void* d_out, int out_size)
{
    const float* x     = (const float*)d_in[0];
    const float* w_qkv = (const float*)d_in[1];
    const float* b_qkv = (const float*)d_in[2];
    const float* w_o   = (const float*)d_in[3];
    const float* b_o   = (const float*)d_in[4];
    float* out = (float*)d_out;

    float *qkv, *attn, *xp, *wqkvp, *wop;
    cudaGetSymbolAddress((void**)&qkv,   g_qkv);
    cudaGetSymbolAddress((void**)&attn,  g_attn);
    cudaGetSymbolAddress((void**)&xp,    g_xp);
    cudaGetSymbolAddress((void**)&wqkvp, g_wqkvp);
    cudaGetSymbolAddress((void**)&wop,   g_wop);

    const int M = B_SZ * S_LEN;   // 4096
    const int gemm_smem = 4 * GSTAGE * (int)sizeof(unsigned);     // 81920
    const int attn_smem = ATTN_SMEM_W * (int)sizeof(unsigned);    // 110592

    static int attr_set = 0;
    if (!attr_set) {
        cudaFuncSetAttribute(gemm_tc<0>,
                             cudaFuncAttributeMaxDynamicSharedMemorySize, gemm_smem);
        cudaFuncSetAttribute(gemm_tc<1>,
                             cudaFuncAttributeMaxDynamicSharedMemorySize, gemm_smem);
        cudaFuncSetAttribute(attn_tc,
                             cudaFuncAttributeMaxDynamicSharedMemorySize, attn_smem);
        attr_set = 1;
    }

    // 0) pre-pass: tf32 + k-pair permutation
    {
        const int ng_x  = B_SZ * S_LEN * E_DIM / 8;   // 1048576
        const int ng_wq = QKV_DIM * E_DIM / 8;        // 393216
        const int ng_wo = E_DIM * E_DIM / 8;          // 131072
        prep_tf32<<<(ng_x  + 255) / 256, 256>>>(x,     xp,    ng_x);
        prep_tf32<<<(ng_wq + 255) / 256, 256>>>(w_qkv, wqkvp, ng_wq);
        prep_tf32<<<(ng_wo + 255) / 256, 256>>>(w_o,   wop,   ng_wo);
    }

    // 1) QKV projection -> tf32 bits, q/k d-permuted
    gemm_tc<1><<<dim3(QKV_DIM / 128, M / 128), 256, gemm_smem>>>(
        xp, wqkvp, b_qkv, qkv, M, QKV_DIM, E_DIM);

    // 2) Flash attention -> tf32 bits, k-permuted
    attn_tc<<<dim3(S_LEN / 128, H_NUM, B_SZ), 256, attn_smem>>>(qkv, attn);

    // 3) Output projection -> final fp32
    gemm_tc<0><<<dim3(E_DIM / 128, M / 128), 256, gemm_smem>>>(
        attn, wop, b_o, out, M, E_DIM, E_DIM);
}

// round 11
// speedup vs baseline: 2.0228x; 1.0314x over previous
#include <cuda_runtime.h>
#include <math.h>

#define B_SZ   2
#define S_LEN  2048
#define E_DIM  1024
#define H_NUM  16
#define D_HEAD 64
#define QKV_DIM 3072   // 3 * E_DIM

// Scratch (allocation-free rule: device globals)
__device__ float g_qkv[B_SZ * S_LEN * QKV_DIM];   // [B,S,3E] tf32 bits, q/k d-permuted
__device__ float g_vT[B_SZ * H_NUM * D_HEAD * S_LEN]; // V^T [b][h][d][s], s pair-permuted
__device__ float g_attn[B_SZ * S_LEN * E_DIM];    // [B,S,E]  tf32 bits, k-permuted
__device__ float g_xp[B_SZ * S_LEN * E_DIM];      // x, tf32 bits, k-permuted
__device__ float g_wqkvp[QKV_DIM * E_DIM];        // w_qkv, tf32 bits, k-permuted
__device__ float g_wop[E_DIM * E_DIM];            // w_o, tf32 bits, k-permuted

// ---------------------------------------------------------------------------
// helpers
// ---------------------------------------------------------------------------
__device__ __forceinline__ unsigned f2tf(float f) {
    unsigned u;
    asm("cvt.rna.tf32.f32 %0, %1;" : "=r"(u) : "f"(f));
    return u;
}
__device__ __forceinline__ float tfbits(float f) { return __uint_as_float(f2tf(f)); }

__device__ __forceinline__ float ex2(float x) {
    float r;
    asm("ex2.approx.f32 %0, %1;" : "=f"(r) : "f"(x));
    return r;
}

// D += A(16x8 tf32 row) * B(8x8 tf32 col), fp32 accumulate, in-place
__device__ __forceinline__ void mma8(float* d, const unsigned* a, const unsigned* b) {
    asm volatile(
        "mma.sync.aligned.m16n8k8.row.col.f32.tf32.tf32.f32 "
        "{%0,%1,%2,%3},{%4,%5,%6,%7},{%8,%9},{%0,%1,%2,%3};"
        : "+f"(d[0]), "+f"(d[1]), "+f"(d[2]), "+f"(d[3])
        : "r"(a[0]), "r"(a[1]), "r"(a[2]), "r"(a[3]), "r"(b[0]), "r"(b[1]));
}

__device__ __forceinline__ void cpa16(const void* smem_dst, const void* gmem_src) {
    unsigned a = (unsigned)__cvta_generic_to_shared(smem_dst);
    asm volatile("cp.async.cg.shared.global [%0], [%1], 16;" :: "r"(a), "l"(gmem_src));
}
#define CP_COMMIT() asm volatile("cp.async.commit_group;")
#define CP_WAIT0()  asm volatile("cp.async.wait_group 0;")

// ---------------------------------------------------------------------------
// Pre-pass: fp32 -> tf32 bits, permute each 8-group of the contiguous (K) dim
// as [0,4,1,5,2,6,3,7] so MMA k-pairs (qp, qp+4) become physically adjacent.
// ---------------------------------------------------------------------------
__global__ void prep_tf32(const float* __restrict__ src, float* __restrict__ dst,
                          int ngroups)
{
    const int i = blockIdx.x * blockDim.x + threadIdx.x;
    if (i >= ngroups) return;
    const float4 a = *(const float4*)&src[(size_t)i * 8];
    const float4 b = *(const float4*)&src[(size_t)i * 8 + 4];
    float4 o0, o1;
    o0.x = tfbits(a.x); o0.y = tfbits(b.x); o0.z = tfbits(a.y); o0.w = tfbits(b.y);
    o1.x = tfbits(a.z); o1.y = tfbits(b.z); o1.z = tfbits(a.w); o1.w = tfbits(b.w);
    *(float4*)&dst[(size_t)i * 8]     = o0;
    *(float4*)&dst[(size_t)i * 8 + 4] = o1;
}

// ---------------------------------------------------------------------------
// Tensor-core GEMM: C[M,N] = A[M,K] @ W[N,K]^T + bias[N]
// A, W already tf32 bits with permuted K. 128x128x32 tiles, 8 warps,
// warp tile 64x32. cp.async 2-stage, LDS.64 frag loads, no inner-loop cvt.
// MODE 0: output fp32 identity (final). MODE 1: q/k sections (col%192<128)
// -> C tf32 bits d-permuted; v sections (col%192>=128) -> VT transposed
// [b][h][d][s] with s pair-permuted, tf32 bits.
// ---------------------------------------------------------------------------
#define GS 40                 // 40 mod 32 == 8 -> conflict-free LDS.64 phases
#define GSTAGE (128 * GS)     // 5120 words per matrix per stage

template<int MODE>
__global__ __launch_bounds__(256, 2)
void gemm_tc(const float* __restrict__ A, const float* __restrict__ W,
             const float* __restrict__ bias, float* __restrict__ C,
             float* __restrict__ VT, int M, int N, int K)
{
    extern __shared__ unsigned gsm[];   // [2][A:GSTAGE | B:GSTAGE]

    const int tid  = threadIdx.x;
    const int lane = tid & 31;
    const int w    = tid >> 5;
    const int wr   = w >> 2;     // 0..1
    const int wc   = w & 3;      // 0..3
    const int g    = lane >> 2;
    const int qp   = lane & 3;
    const int m0   = blockIdx.y * 128;
    const int n0   = blockIdx.x * 128;

    auto issue = [&](int t) {
        const int k0 = t * 32;
        unsigned* dst = &gsm[(t & 1) * 2 * GSTAGE];
#pragma unroll
        for (int i = 0; i < 4; i++) {
            const int lin = tid + i * 256;
            const int r   = lin >> 3;          // 0..127
            const int c4  = (lin & 7) * 4;     // 0..28
            cpa16(&dst[r * GS + c4],          &A[(size_t)(m0 + r) * K + k0 + c4]);
            cpa16(&dst[GSTAGE + r * GS + c4], &W[(size_t)(n0 + r) * K + k0 + c4]);
        }
        CP_COMMIT();
    };

    float acc[4][4][4];
#pragma unroll
    for (int mt = 0; mt < 4; mt++)
#pragma unroll
        for (int nt = 0; nt < 4; nt++)
#pragma unroll
            for (int x = 0; x < 4; x++) acc[mt][nt][x] = 0.f;

    issue(0);

    const int niters = K >> 5;
    for (int t = 0; t < niters; t++) {
        CP_WAIT0();
        __syncthreads();
        if (t + 1 < niters) issue(t + 1);

        const unsigned* As = &gsm[(t & 1) * 2 * GSTAGE];
        const unsigned* Bs = As + GSTAGE;

#pragma unroll
        for (int ks = 0; ks < 4; ks++) {
            const int kb = ks * 8;
            unsigned af[4][4];
#pragma unroll
            for (int mt = 0; mt < 4; mt++) {
                const int r0 = (wr * 64 + mt * 16 + g) * GS + kb + 2 * qp;
                const uint2 u0 = *(const uint2*)&As[r0];
                const uint2 u1 = *(const uint2*)&As[r0 + 8 * GS];
                af[mt][0] = u0.x; af[mt][1] = u1.x;
                af[mt][2] = u0.y; af[mt][3] = u1.y;
            }
            unsigned bf[4][2];
#pragma unroll
            for (int nt = 0; nt < 4; nt++) {
                const uint2 v = *(const uint2*)&Bs[(wc * 32 + nt * 8 + g) * GS + kb + 2 * qp];
                bf[nt][0] = v.x; bf[nt][1] = v.y;
            }
#pragma unroll
            for (int mt = 0; mt < 4; mt++)
#pragma unroll
                for (int nt = 0; nt < 4; nt++)
                    mma8(acc[mt][nt], af[mt], bf[nt]);
        }
    }

    // epilogue (c-frag: rows g,g+8; logical cols qp*2, qp*2+1)
    const int p0 = (qp & 1) * 4 + (qp >> 1);   // physical slot of logical 2qp
#pragma unroll
    for (int nt = 0; nt < 4; nt++) {
        const int cb = n0 + wc * 32 + nt * 8;      // 8-group base
        const float2 bb = *(const float2*)&bias[cb + qp * 2];
#pragma unroll
        for (int mt = 0; mt < 4; mt++) {
            const int rr = m0 + wr * 64 + mt * 16 + g;
            const float v00 = acc[mt][nt][0] + bb.x;
            const float v01 = acc[mt][nt][1] + bb.y;
            const float v10 = acc[mt][nt][2] + bb.x;
            const float v11 = acc[mt][nt][3] + bb.y;
            if (MODE == 0) {
                *(float2*)&C[(size_t)rr * N + cb + qp * 2]       = make_float2(v00, v01);
                *(float2*)&C[(size_t)(rr + 8) * N + cb + qp * 2] = make_float2(v10, v11);
            } else {
                const int sec = cb % 192;
                if (sec < 128) {
                    // q/k: tf32 bits, d-permuted into C
                    C[(size_t)rr * N + cb + p0]           = tfbits(v00);
                    C[(size_t)rr * N + cb + p0 + 2]       = tfbits(v01);
                    C[(size_t)(rr + 8) * N + cb + p0]     = tfbits(v10);
                    C[(size_t)(rr + 8) * N + cb + p0 + 2] = tfbits(v11);
                } else {
                    // v: transposed into VT[b][h][d][s], s pair-permuted
                    const int hh = cb / 192;
                    const int d0 = sec - 128 + qp * 2;
                    const int bi = rr >> 11;           // batch
                    const int s  = rr & 2047;
                    const int s7 = s & 7;
                    const int sp = (s & ~7) | (s7 < 4 ? 2 * s7 : 2 * (s7 - 4) + 1);
                    float* vb = &VT[(((size_t)bi * H_NUM + hh) * 64 + d0) * S_LEN];
                    vb[sp]             = tfbits(v00);
                    vb[S_LEN + sp]     = tfbits(v01);
                    vb[sp + 8]         = tfbits(v10);   // s+8: same perm offset
                    vb[S_LEN + sp + 8] = tfbits(v11);
                }
            }
        }
    }
}

// ---------------------------------------------------------------------------
// Flash attention, tensor cores. qkv holds tf32 bits (q/k d-permuted);
// V comes from g_vT (transposed, s pair-permuted) -> PV B-frags are LDS.64.
// Softmax in base-2 (log2e folded into Q scale), raw MUFU.EX2.
// ---------------------------------------------------------------------------
#define AQ 72
#define AK 72
#define AV 72
#define KV_STAGE (64 * AK + 64 * AV)            // 9216 words
#define ATTN_SMEM_W (128 * AQ + 2 * KV_STAGE)   // 27648 words = 110592 B

__global__ __launch_bounds__(256, 2)
void attn_tc(const float* __restrict__ qkv, const float* __restrict__ vT,
             float* __restrict__ out)
{
    extern __shared__ unsigned smu[];

    const int tid  = threadIdx.x;
    const int lane = tid & 31;
    const int w    = tid >> 5;
    const int g    = lane >> 2;
    const int qp   = lane & 3;
    const int q0   = blockIdx.x * 128;
    const int h    = blockIdx.y;
    const int b    = blockIdx.z;

    const size_t base  = (size_t)b * S_LEN * QKV_DIM + (size_t)h * (3 * D_HEAD);
    const size_t vbase = ((size_t)b * H_NUM + h) * 64 * (size_t)S_LEN;

    auto issue_kv = [&](int kt) {
        const int j0  = kt * 64;
        const int off = 128 * AQ + (kt & 1) * KV_STAGE;
#pragma unroll
        for (int i = 0; i < 4; i++) {
            const int lin = tid + i * 256;
            const int r   = lin >> 4;          // 0..63 (K: j row; V: d row)
            const int c4  = (lin & 15) * 4;    // 0..60
            cpa16(&smu[off + r * AK + c4],
                  &qkv[base + (size_t)(j0 + r) * QKV_DIM + D_HEAD + c4]);     // K
            cpa16(&smu[off + 64 * AK + r * AV + c4],
                  &vT[vbase + (size_t)r * S_LEN + j0 + c4]);                  // V^T
        }
        CP_COMMIT();
    };

    // ---- stage Q: fold 0.125 * log2(e) scale, re-round to tf32 ----
    const float QSC = 0.125f * 1.4426950408889634f;
#pragma unroll
    for (int i = 0; i < 8; i++) {
        const int lin = tid + i * 256;
        const int r   = lin >> 4;
        const int d4  = (lin & 15) * 4;
        const float4 q = *(const float4*)&qkv[base + (size_t)(q0 + r) * QKV_DIM + d4];
        uint4 u;
        u.x = f2tf(q.x * QSC); u.y = f2tf(q.y * QSC);
        u.z = f2tf(q.z * QSC); u.w = f2tf(q.w * QSC);
        *(uint4*)&smu[r * AQ + d4] = u;
    }
    issue_kv(0);

    float o[8][4];
#pragma unroll
    for (int nt = 0; nt < 8; nt++)
#pragma unroll
        for (int x = 0; x < 4; x++) o[nt][x] = 0.f;
    float m0v = -INFINITY, m1v = -INFINITY, l0 = 0.f, l1 = 0.f;

    const int pr0   = w * 16 + g;
    const int psrc0 = (lane & ~3) | (qp >> 1);
    const int psrc1 = psrc0 + 2;
    const bool podd = qp & 1;

    for (int kt = 0; kt < S_LEN / 64; kt++) {
        CP_WAIT0();
        __syncthreads();
        if (kt + 1 < S_LEN / 64) issue_kv(kt + 1);

        const int off = 128 * AQ + (kt & 1) * KV_STAGE;
        const unsigned* Kf = &smu[off];
        const unsigned* Vf = &smu[off + 64 * AK];

        // ---- S = Q @ K^T (LDS.64 frags, no cvt) ----
        float s[8][4];
#pragma unroll
        for (int nt = 0; nt < 8; nt++)
#pragma unroll
            for (int x = 0; x < 4; x++) s[nt][x] = 0.f;

#pragma unroll
        for (int ks = 0; ks < 8; ks++) {
            const int kb = ks * 8;
            const int r0 = pr0 * AQ + kb + 2 * qp;
            const uint2 u0 = *(const uint2*)&smu[r0];
            const uint2 u1 = *(const uint2*)&smu[r0 + 8 * AQ];
            unsigned aq[4] = {u0.x, u1.x, u0.y, u1.y};
#pragma unroll
            for (int nt = 0; nt < 8; nt++) {
                const uint2 v = *(const uint2*)&Kf[(nt * 8 + g) * AK + kb + 2 * qp];
                unsigned bk[2] = {v.x, v.y};
                mma8(s[nt], aq, bk);
            }
        }

        // ---- online softmax (base-2; rows g, g+8 of warp tile) ----
        float rm0 = s[0][0], rm1 = s[0][2];
#pragma unroll
        for (int nt = 0; nt < 8; nt++) {
            rm0 = fmaxf(rm0, fmaxf(s[nt][0], s[nt][1]));
            rm1 = fmaxf(rm1, fmaxf(s[nt][2], s[nt][3]));
        }
        rm0 = fmaxf(rm0, __shfl_xor_sync(0xffffffffu, rm0, 1));
        rm0 = fmaxf(rm0, __shfl_xor_sync(0xffffffffu, rm0, 2));
        rm1 = fmaxf(rm1, __shfl_xor_sync(0xffffffffu, rm1, 1));
        rm1 = fmaxf(rm1, __shfl_xor_sync(0xffffffffu, rm1, 2));

        const float mn0 = fmaxf(m0v, rm0);
        const float mn1 = fmaxf(m1v, rm1);
        const float corr0 = ex2(m0v - mn0);
        const float corr1 = ex2(m1v - mn1);
        m0v = mn0; m1v = mn1;

        float rs0 = 0.f, rs1 = 0.f;
#pragma unroll
        for (int nt = 0; nt < 8; nt++) {
            s[nt][0] = ex2(s[nt][0] - mn0);
            s[nt][1] = ex2(s[nt][1] - mn0);
            s[nt][2] = ex2(s[nt][2] - mn1);
            s[nt][3] = ex2(s[nt][3] - mn1);
            rs0 += s[nt][0] + s[nt][1];
            rs1 += s[nt][2] + s[nt][3];
        }
        rs0 += __shfl_xor_sync(0xffffffffu, rs0, 1);
        rs0 += __shfl_xor_sync(0xffffffffu, rs0, 2);
        rs1 += __shfl_xor_sync(0xffffffffu, rs1, 1);
        rs1 += __shfl_xor_sync(0xffffffffu, rs1, 2);
        l0 = l0 * corr0 + rs0;
        l1 = l1 * corr1 + rs1;

#pragma unroll
        for (int nt = 0; nt < 8; nt++) {
            o[nt][0] *= corr0; o[nt][1] *= corr0;
            o[nt][2] *= corr1; o[nt][3] *= corr1;
        }

        // ---- O += P @ V : P via quad shuffles, V^T frags via LDS.64 ----
#pragma unroll
        for (int nt = 0; nt < 8; nt++) {   // nt = k-step of PV (8 j-columns)
            const float x0 = __shfl_sync(0xffffffffu, s[nt][0], psrc0);
            const float x1 = __shfl_sync(0xffffffffu, s[nt][1], psrc0);
            const float x2 = __shfl_sync(0xffffffffu, s[nt][2], psrc0);
            const float x3 = __shfl_sync(0xffffffffu, s[nt][3], psrc0);
            const float y0 = __shfl_sync(0xffffffffu, s[nt][0], psrc1);
            const float y1 = __shfl_sync(0xffffffffu, s[nt][1], psrc1);
            const float y2 = __shfl_sync(0xffffffffu, s[nt][2], psrc1);
            const float y3 = __shfl_sync(0xffffffffu, s[nt][3], psrc1);
            unsigned ap[4];
            ap[0] = f2tf(podd ? x1 : x0);
            ap[1] = f2tf(podd ? x3 : x2);
            ap[2] = f2tf(podd ? y1 : y0);
            ap[3] = f2tf(podd ? y3 : y2);
#pragma unroll
            for (int nd = 0; nd < 8; nd++) {
                const uint2 vv = *(const uint2*)&Vf[(nd * 8 + g) * AV + nt * 8 + 2 * qp];
                unsigned bb[2] = {vv.x, vv.y};
                mma8(o[nd], ap, bb);
            }
        }
    }

    // ---- normalize + write tf32 bits, k-permuted (feeds O-proj) ----
    const float inv0 = 1.f / l0;
    const float inv1 = 1.f / l1;
    const int row0 = q0 + w * 16 + g;
    const int p0 = (qp & 1) * 4 + (qp >> 1);
#pragma unroll
    for (int nt = 0; nt < 8; nt++) {
        const int cb = h * D_HEAD + nt * 8;
        float* r0p = &out[((size_t)b * S_LEN + row0) * E_DIM + cb];
        float* r1p = &out[((size_t)b * S_LEN + row0 + 8) * E_DIM + cb];
        r0p[p0]     = tfbits(o[nt][0] * inv0);
        r0p[p0 + 2] = tfbits(o[nt][1] * inv0);
        r1p[p0]     = tfbits(o[nt][2] * inv1);
        r1p[p0 + 2] = tfbits(o[nt][3] * inv1);
    }
}

// ---------------------------------------------------------------------------
extern "C" void kernel_launch(void* const* d_in, const int* in_sizes, int n_in,
                              void* d_out, int out_size)
{
    const float* x     = (const float*)d_in[0];
    const float* w_qkv = (const float*)d_in[1];
    const float* b_qkv = (const float*)d_in[2];
    const float* w_o   = (const float*)d_in[3];
    const float* b_o   = (const float*)d_in[4];
    float* out = (float*)d_out;

    float *qkv, *vT, *attn, *xp, *wqkvp, *wop;
    cudaGetSymbolAddress((void**)&qkv,   g_qkv);
    cudaGetSymbolAddress((void**)&vT,    g_vT);
    cudaGetSymbolAddress((void**)&attn,  g_attn);
    cudaGetSymbolAddress((void**)&xp,    g_xp);
    cudaGetSymbolAddress((void**)&wqkvp, g_wqkvp);
    cudaGetSymbolAddress((void**)&wop,   g_wop);

    const int M = B_SZ * S_LEN;   // 4096
    const int gemm_smem = 4 * GSTAGE * (int)sizeof(unsigned);     // 81920
    const int attn_smem = ATTN_SMEM_W * (int)sizeof(unsigned);    // 110592

    static int attr_set = 0;
    if (!attr_set) {
        cudaFuncSetAttribute(gemm_tc<0>,
                             cudaFuncAttributeMaxDynamicSharedMemorySize, gemm_smem);
        cudaFuncSetAttribute(gemm_tc<1>,
                             cudaFuncAttributeMaxDynamicSharedMemorySize, gemm_smem);
        cudaFuncSetAttribute(attn_tc,
                             cudaFuncAttributeMaxDynamicSharedMemorySize, attn_smem);
        attr_set = 1;
    }

    // 0) pre-pass: tf32 + k-pair permutation
    {
        const int ng_x  = B_SZ * S_LEN * E_DIM / 8;   // 1048576
        const int ng_wq = QKV_DIM * E_DIM / 8;        // 393216
        const int ng_wo = E_DIM * E_DIM / 8;          // 131072
        prep_tf32<<<(ng_x  + 255) / 256, 256>>>(x,     xp,    ng_x);
        prep_tf32<<<(ng_wq + 255) / 256, 256>>>(w_qkv, wqkvp, ng_wq);
        prep_tf32<<<(ng_wo + 255) / 256, 256>>>(w_o,   wop,   ng_wo);
    }

    // 1) QKV projection -> q/k into g_qkv (d-permuted), v into g_vT (transposed)
    gemm_tc<1><<<dim3(QKV_DIM / 128, M / 128), 256, gemm_smem>>>(
        xp, wqkvp, b_qkv, qkv, vT, M, QKV_DIM, E_DIM);

    // 2) Flash attention -> tf32 bits, k-permuted
    attn_tc<<<dim3(S_LEN / 128, H_NUM, B_SZ), 256, attn_smem>>>(qkv, vT, attn);

    // 3) Output projection -> final fp32
    gemm_tc<0><<<dim3(E_DIM / 128, M / 128), 256, gemm_smem>>>(
        attn, wop, b_o, out, nullptr, M, E_DIM, E_DIM);
}